// round 11
// baseline (speedup 1.0000x reference)
#include <cuda_runtime.h>

// Tensor: (1024, 1024, 3, 3) fp32
#define OC_N    1024
#define IC_N    1024
#define N_TOT   (OC_N * IC_N * 9)    // 9437184
#define N_VEC4  (N_TOT / 4)          // 2359296
#define MAX_GRID 2304                // 2304*256 threads * 4 float4 = N_VEC4

// Monotone max accumulator: positive floats order as their int bits.
// atomicMax re-applies the same max on every graph replay -> deterministic.
__device__ int g_maxabs_bits;

// ---------------------------------------------------------------------------
// Pass A: global max|t| via per-block reduce + one atomicMax per block.
__global__ void __launch_bounds__(256) k_maxabs(const float4* __restrict__ in) {
    const int base = blockIdx.x * 256 + threadIdx.x;
    const int stride = MAX_GRID * 256;
    float m = 0.0f;
#pragma unroll
    for (int k = 0; k < 4; k++) {
        float4 v = in[base + k * stride];
        m = fmaxf(m, fmaxf(fmaxf(fabsf(v.x), fabsf(v.y)),
                           fmaxf(fabsf(v.z), fabsf(v.w))));
    }
#pragma unroll
    for (int o = 16; o > 0; o >>= 1)
        m = fmaxf(m, __shfl_xor_sync(0xFFFFFFFFu, m, o));
    __shared__ float sm[8];
    if ((threadIdx.x & 31) == 0) sm[threadIdx.x >> 5] = m;
    __syncthreads();
    if (threadIdx.x == 0) {
        m = sm[0];
#pragma unroll
        for (int i = 1; i < 8; i++) m = fmaxf(m, sm[i]);
        atomicMax(&g_maxabs_bits, __float_as_int(m));
    }
}

// ---------------------------------------------------------------------------
// Fused pass: one block = one OC channel (1024 rows of 9 = 9216 elems).
// 6 blocks/SM: regs<=42 (launch_bounds) AND smem 37,676B (+1KB reserve
// fits 228KB/6 = 38,912B). Phase 1 stores each element ONCE (flipped value
// computed in registers) -- no smem RMW flip pass.
__global__ void __launch_bounds__(256, 6) k_main(const float* __restrict__ in,
                                                 float* __restrict__ out) {
    __shared__ __align__(16) float tile[9216];   // 36864 B
    __shared__ unsigned shist[128];              // 512 B (also fallback scratch)
    __shared__ unsigned sbk[64];                 // 256 B compact bucket-B list
    __shared__ float    swred[8];
    __shared__ int      s_B;
    __shared__ unsigned s_c1, s_cnt;

    const int tid = threadIdx.x;

    // Per-block scale (uniform): IEEE div of the SAME max bits everywhere.
    const float scl = __fdiv_rn(__int_as_float(g_maxabs_bits), 127.0f);
    const float rcp = __frcp_rn(scl);

    const float4* in4 = reinterpret_cast<const float4*>(in)
                        + (size_t)blockIdx.x * 2304;
    float4* t4 = reinterpret_cast<float4*>(tile);
#pragma unroll
    for (int i = tid; i < 2304; i += 256) t4[i] = in4[i];
    if (tid < 128) shist[tid] = 0u;
    if (tid == 0)  s_cnt = 0u;
    __syncthreads();

    // ---- Phase 1: 4 rows per thread (rows q*256+tid); store-once mode ----
    float resid4 = 0.0f;
    unsigned mykey[4];
#pragma unroll
    for (int q = 0; q < 4; q++) {
        const int rbase = q * 2304 + tid * 9;    // 9-stride LDS: conflict-free
        float r[9], p[9];
        float esum = 0.0f;
#pragma unroll
        for (int i = 0; i < 9; i++) {
            float t  = tile[rbase + i];
            float q0 = __fmul_rn(t, rcp);                          // Markstein
            float x  = __fmaf_rn(__fmaf_rn(-scl, q0, t), rcp, q0); // == t/scl
            x = fminf(fmaxf(x, -127.0f), 127.0f);
            r[i] = rintf(x);           // round-half-to-even == jnp.round
            float re = __fadd_rn(r[i], -x);
            esum = __fadd_rn(esum, re);
            p[i] = re;                 // raw error, signed (converted below)
        }
        const int   nf = (int)rintf(fabsf(esum));
        const bool  up = (esum < 0.0f);
        const float d1 = up ? 1.0f : -1.0f;
#pragma unroll
        for (int i = 0; i < 9; i++)
            p[i] = fmaxf(up ? -p[i] : p[i], 0.0f);

        // pairwise stable rank (tie -> lower index outranks)
        int rank[9];
#pragma unroll
        for (int j = 0; j < 9; j++) rank[j] = j;
#pragma unroll
        for (int i = 0; i < 8; i++)
#pragma unroll
            for (int j = i + 1; j < 9; j++) {
                int gg = (int)(p[j] > p[i]);
                rank[i] += gg;
                rank[j] -= gg;
            }
        int bi = -1;
#pragma unroll
        for (int i = 0; i < 9; i++) {
            tile[rbase + i] = (rank[i] < nf) ? __fadd_rn(r[i], d1) : r[i];
            if (rank[i] == nf - 1) bi = i;                  // boundary
        }
        resid4 = __fadd_rn(resid4, __fmaf_rn((float)nf, d1, esum));

        // 32-bit candidate key: dir(1) | prio17 | (9216-elemFlat)(14)
        // |re[bi]+d1| == fadd(1, -p[bi]) bit-exactly (RN sign-symmetric),
        // value in [0.5,1): exponent fixed -> mantissa alone orders it.
        unsigned cand = 0u;
        if (bi >= 0) {
            float a = __fadd_rn(1.0f, -p[bi]);
            unsigned mant = __float_as_uint(a) & 0x7FFFFFu;
            cand = ((up ? 1u : 0u) << 31) | ((mant >> 6) << 14)
                 | (unsigned)(9216 - (rbase + bi));
        }
        mykey[q] = cand;
    }

    // ---- Phase 2: block residual reduce (fixed, deterministic order) ----
#pragma unroll
    for (int o = 16; o > 0; o >>= 1)
        resid4 += __shfl_xor_sync(0xFFFFFFFFu, resid4, o);
    if ((tid & 31) == 0) swred[tid >> 5] = resid4;
    __syncthreads();
    float esum_c = swred[0];
#pragma unroll
    for (int i = 1; i < 8; i++) esum_c = __fadd_rn(esum_c, swred[i]);
    const int nfc = (int)rintf(fabsf(esum_c));   // uniform across block

    if (nfc != 0) {                              // uniform branch
        const bool upc = (esum_c < 0.0f);
        // stage-2 up-flip reverts a stage-1 DOWN-flipped boundary (dir bit 0)
        const unsigned want   = upc ? 0u : 1u;
        const float    dpatch = upc ? 1.0f : -1.0f;   // pre-scale units

        // ---- 3a: filter in registers + 128-bucket histogram (key>>24) ----
#pragma unroll
        for (int q = 0; q < 4; q++) {
            unsigned k = mykey[q];
            unsigned kk = (k != 0u && (k >> 31) == want) ? (k & 0x7FFFFFFFu)
                                                         : 0u;
            mykey[q] = kk;
            if (kk != 0u) atomicAdd(&shist[kk >> 24], 1u);
        }
        __syncthreads();

        // ---- 3b: warp 0 suffix-scan -> threshold bucket B, c1 ----
        if (tid < 32) {
            const int lane = tid;
            const int g = 31 - lane;             // lane owns buckets 4g..4g+3
            unsigned s = 0u;
#pragma unroll
            for (int b = 0; b < 4; b++) s += shist[g * 4 + b];
            unsigned C = s;
#pragma unroll
            for (int o = 1; o < 32; o <<= 1) {
                unsigned v = __shfl_up_sync(0xFFFFFFFFu, C, o);
                if (lane >= o) C += v;
            }
            const unsigned ball = __ballot_sync(0xFFFFFFFFu,
                                                C >= (unsigned)nfc);
            const int lsel = (ball == 0u) ? 31 : (__ffs(ball) - 1);
            const unsigned Cl = __shfl_sync(0xFFFFFFFFu, C, lsel);
            const unsigned sl = __shfl_sync(0xFFFFFFFFu, s, lsel);
            const int gsel = 31 - lsel;
            unsigned hb[4];
#pragma unroll
            for (int b = 0; b < 4; b++) hb[b] = shist[gsel * 4 + b];
            int B = gsel * 4;
            unsigned c1 = Cl - sl;
            bool found = false;
#pragma unroll
            for (int b = 3; b >= 1; b--) {
                if (!found) {
                    if (c1 + hb[b] >= (unsigned)nfc) {
                        B = gsel * 4 + b; found = true;
                    } else c1 += hb[b];
                }
            }
            if (lane == 0) { s_B = B; s_c1 = c1; }
        }
        __syncthreads();
        const unsigned B  = (unsigned)s_B;
        const unsigned c1 = s_c1;

        // ---- 3c: patch buckets > B in tile; ticket bucket-B keys to sbk ----
#pragma unroll
        for (int q = 0; q < 4; q++) {
            unsigned kk = mykey[q];
            if (kk != 0u) {
                unsigned b = kk >> 24;
                if (b > B) {
                    tile[9216 - (int)(kk & 0x3FFFu)] += dpatch; // disjoint
                } else if (b == B) {
                    unsigned idx = atomicAdd(&s_cnt, 1u);
                    if (idx < 64u) sbk[idx] = kk;
                }
            }
        }
        __syncthreads();
        const unsigned cnt = s_cnt;
        const int k2 = nfc - (int)c1;            // >= 1 by construction

        if (cnt <= 64u) {
            // ---- 3d: warp 0 serial pick loop over compact list (tiny) ----
            if (tid < 32) {
                const int lane = tid;
                unsigned key[2];
#pragma unroll
                for (int j = 0; j < 2; j++) {
                    unsigned idx = j * 32 + lane;
                    key[j] = (idx < cnt) ? sbk[idx] : 0u;
                }
                unsigned lmax = umax(key[0], key[1]);
                for (int it = 0; it < k2; it++) {
                    const unsigned m = __reduce_max_sync(0xFFFFFFFFu, lmax);
                    if (m == 0u) break;          // exhausted (safe clamp)
                    if (lane == 0)
                        tile[9216 - (int)(m & 0x3FFFu)] += dpatch;
                    unsigned k0 = (key[0] < m) ? key[0] : 0u;
                    unsigned k1 = (key[1] < m) ? key[1] : 0u;
                    lmax = umax(k0, k1);
                }
            }
            __syncthreads();
        } else {
            // ---- Fallback (adversarial only): block-wide serial top-k2 ----
            unsigned lk[4];
#pragma unroll
            for (int q = 0; q < 4; q++)
                lk[q] = (mykey[q] != 0u && (mykey[q] >> 24) == B) ? mykey[q]
                                                                  : 0u;
            for (int it = 0; it < k2; it++) {
                unsigned lm = umax(umax(lk[0], lk[1]), umax(lk[2], lk[3]));
#pragma unroll
                for (int o = 16; o > 0; o >>= 1)
                    lm = umax(lm, __shfl_xor_sync(0xFFFFFFFFu, lm, o));
                if ((tid & 31) == 0) shist[tid >> 5] = lm;
                __syncthreads();
                if (tid == 0) {
                    unsigned m = shist[0];
#pragma unroll
                    for (int i = 1; i < 8; i++) m = umax(m, shist[i]);
                    shist[8] = m;
                }
                __syncthreads();
                const unsigned m = shist[8];     // uniform
                if (m == 0u) break;              // uniform break
#pragma unroll
                for (int q = 0; q < 4; q++) {
                    if (lk[q] == m)              // unique owner
                        tile[9216 - (int)(m & 0x3FFFu)] += dpatch;
                    lk[q] = (lk[q] < m) ? lk[q] : 0u;
                }
                __syncthreads();
            }
            __syncthreads();
        }
    }

    // ---- Phase 4: single scaled write-out ----
    float4* out4 = reinterpret_cast<float4*>(out) + (size_t)blockIdx.x * 2304;
#pragma unroll
    for (int i = tid; i < 2304; i += 256) {
        float4 v = t4[i];
        v.x = __fmul_rn(v.x, scl); v.y = __fmul_rn(v.y, scl);
        v.z = __fmul_rn(v.z, scl); v.w = __fmul_rn(v.w, scl);
        out4[i] = v;
    }
}

// ---------------------------------------------------------------------------
extern "C" void kernel_launch(void* const* d_in, const int* in_sizes, int n_in,
                              void* d_out, int out_size) {
    const float* in  = (const float*)d_in[0];
    float*       out = (float*)d_out;

    k_maxabs<<<MAX_GRID, 256>>>((const float4*)in);
    k_main<<<OC_N, 256>>>(in, out);
}